// round 17
// baseline (speedup 1.0000x reference)
#include <cuda_runtime.h>
#include <cuda_fp16.h>
#include <cstdint>

#define C_DIM   768
#define QKV_DIM 3072
#define BATCH   4
#define SEQ     1024
#define HEADS   12
#define HD      64
#define M_ROWS  (BATCH*SEQ)   // 4096

// -------- scratch (allocation-free: device globals, all fp16) --------
__device__ __half g_x_h[M_ROWS*C_DIM];
__device__ __half g_y_h[M_ROWS*C_DIM];
__device__ __half g_wqkv_h[QKV_DIM*C_DIM];
__device__ __half g_wproj_h[C_DIM*C_DIM];
__device__ __half g_qkvx_h[M_ROWS*QKV_DIM];
__device__ __half g_qkvy_h[M_ROWS*QKV_DIM];
__device__ __half g_attx_h[M_ROWS*C_DIM];
__device__ __half g_atty_h[M_ROWS*C_DIM];

// ============================================================
// helpers
// ============================================================
__device__ __forceinline__ uint32_t smem_u32(const void* p) {
    uint32_t a;
    asm("{ .reg .u64 t; cvta.to.shared.u64 t, %1; cvt.u32.u64 %0, t; }"
        : "=r"(a) : "l"(p));
    return a;
}

__device__ __forceinline__ void ldsm_x4(uint32_t addr, uint32_t& r0, uint32_t& r1,
                                        uint32_t& r2, uint32_t& r3) {
    asm volatile("ldmatrix.sync.aligned.m8n8.x4.shared.b16 {%0,%1,%2,%3}, [%4];"
                 : "=r"(r0), "=r"(r1), "=r"(r2), "=r"(r3) : "r"(addr));
}

__device__ __forceinline__ void ldsm_x4_t(uint32_t addr, uint32_t& r0, uint32_t& r1,
                                          uint32_t& r2, uint32_t& r3) {
    asm volatile("ldmatrix.sync.aligned.m8n8.x4.trans.shared.b16 {%0,%1,%2,%3}, [%4];"
                 : "=r"(r0), "=r"(r1), "=r"(r2), "=r"(r3) : "r"(addr));
}

__device__ __forceinline__ void mma_f16(float* c, const uint32_t* a,
                                        uint32_t b0, uint32_t b1) {
    asm volatile(
        "mma.sync.aligned.m16n8k16.row.col.f32.f16.f16.f32 "
        "{%0,%1,%2,%3}, {%4,%5,%6,%7}, {%8,%9}, {%0,%1,%2,%3};"
        : "+f"(c[0]), "+f"(c[1]), "+f"(c[2]), "+f"(c[3])
        : "r"(a[0]), "r"(a[1]), "r"(a[2]), "r"(a[3]), "r"(b0), "r"(b1));
}

__device__ __forceinline__ void cp_async16(uint32_t saddr, const void* gptr) {
    asm volatile("cp.async.cg.shared.global [%0], [%1], 16;"
                 :: "r"(saddr), "l"(gptr));
}
__device__ __forceinline__ void cp_commit() {
    asm volatile("cp.async.commit_group;" ::: "memory");
}
__device__ __forceinline__ void cp_wait0() { asm volatile("cp.async.wait_group 0;" ::: "memory"); }
__device__ __forceinline__ void cp_wait1() { asm volatile("cp.async.wait_group 1;" ::: "memory"); }

__device__ __forceinline__ uint32_t pack_h2(__half a, __half b) {
    return ((uint32_t)__half_as_ushort(b) << 16) | (uint32_t)__half_as_ushort(a);
}

// fp32 float4 -> fp16 x4
__device__ __forceinline__ uint2 hi4h(float4 v) {
    return make_uint2(pack_h2(__float2half_rn(v.x), __float2half_rn(v.y)),
                      pack_h2(__float2half_rn(v.z), __float2half_rn(v.w)));
}

// ============================================================
// fused fp32 -> fp16 convert kernel (4 arrays, one launch, 4x ILP)
// ============================================================
__device__ __forceinline__ void cvt_one(
    int i,
    const float* __restrict__ s0, __half* __restrict__ d0, int n0,
    const float* __restrict__ s1, __half* __restrict__ d1, int n1,
    const float* __restrict__ s2, __half* __restrict__ d2, int n2,
    const float* __restrict__ s3, __half* __restrict__ d3, int n3)
{
    const float* s; __half* d;
    if (i < n0)                { s = s0; d = d0; }
    else if ((i -= n0) < n1)   { s = s1; d = d1; }
    else if ((i -= n1) < n2)   { s = s2; d = d2; }
    else if ((i -= n2) < n3)   { s = s3; d = d3; }
    else return;
    float4 v = ((const float4*)s)[i];
    ((uint2*)d)[i] = hi4h(v);
}

__global__ __launch_bounds__(256) void cvt4_kernel(
    const float* __restrict__ s0, __half* __restrict__ d0, int n0,
    const float* __restrict__ s1, __half* __restrict__ d1, int n1,
    const float* __restrict__ s2, __half* __restrict__ d2, int n2,
    const float* __restrict__ s3, __half* __restrict__ d3, int n3)
{
    int base = blockIdx.x * 1024 + threadIdx.x;
#pragma unroll
    for (int u = 0; u < 4; u++)
        cvt_one(base + u * 256, s0, d0, n0, s1, d1, n1, s2, d2, n2, s3, d3, n3);
}

// ============================================================
// fp16 mma.sync GEMM (fp32 accum). 1-pass.
// CTA tile 128m x 128n, 8 warps (2m x 4n), warp tile 64x32.
// BK=128 (128 MMAs/warp per stage == attention's proven density),
// 2-deep cp.async ring, 1 sync/stage, 1 CTA/SM (139 KB smem).
// qkv_scale folds +-hd^-0.5 into q chunks.
// ============================================================
#define LDH5 136                       // halves per row (128 + 8 pad)
#define ACH5 (128 * LDH5)              // 17408 halves per array (A or B)
#define STGB5 (2 * ACH5 * 2)           // 69632 bytes per stage
#define GEMM_SMEM (2 * STGB5)          // 139264 -> 1 CTA/SM

__global__ __launch_bounds__(256, 1) void gemm_mma(
    const __half* __restrict__ A0, const __half* __restrict__ A1,
    const __half* __restrict__ B,
    const float* __restrict__ bias,
    float* __restrict__ Cf0, float* __restrict__ Cf1,
    __half* __restrict__ Ch0, __half* __restrict__ Ch1,
    int M, int N, int K, int n_lim1, int qkv_scale)
{
    extern __shared__ __align__(16) __half sh[];
    const int tid  = threadIdx.x;
    const int wid  = tid >> 5;
    const int lane = tid & 31;
    const int m0 = blockIdx.y * 128, n0 = blockIdx.x * 128;
    if (blockIdx.z && n0 >= n_lim1) return;   // vy skip for y-QKV
    const int wm = (wid & 1) * 64;
    const int wn = (wid >> 1) * 32;
    const int S  = K / 128;

    const __half* A = blockIdx.z ? A1 : A0;

    const uint32_t sbase = smem_u32(sh);

    auto issue_stage = [&](int s, int buf) {
        const int kb = s * 128;
        const uint32_t so = sbase + (uint32_t)buf * STGB5;
#pragma unroll
        for (int j = 0; j < 8; j++) {
            int cid = tid + j * 256;             // 0..2047
            int row = cid >> 4;                  // 0..127
            int c8  = (cid & 15) << 3;           // 0..120 halves
            cp_async16(so + (uint32_t)(row * LDH5 + c8) * 2u,
                       A + (size_t)(m0 + row) * K + kb + c8);
            cp_async16(so + (uint32_t)(ACH5 + row * LDH5 + c8) * 2u,
                       B + (size_t)(n0 + row) * K + kb + c8);
        }
    };

    float acc[4][4][4];
#pragma unroll
    for (int i = 0; i < 4; i++)
#pragma unroll
        for (int j = 0; j < 4; j++)
#pragma unroll
            for (int r = 0; r < 4; r++) acc[i][j][r] = 0.f;

    const int a_off = (wm + (lane & 15)) * LDH5 + ((lane >> 4) << 3);
    const int b_off = (wn + ((lane >> 4) << 3) + (lane & 7)) * LDH5 + (((lane >> 3) & 1) << 3);

    issue_stage(0, 0); cp_commit();
    issue_stage(1, 1); cp_commit();

    for (int s = 0; s < S; s++) {
        if (s + 1 < S) cp_wait1();
        else           cp_wait0();
        __syncthreads();

        const uint32_t stg = sbase + (uint32_t)((s & 1) * STGB5);

#pragma unroll
        for (int ks = 0; ks < 8; ks++) {
            const uint32_t kofs = (uint32_t)(ks * 16) * 2u;
            uint32_t ah[4][4], bh[4][2];
#pragma unroll
            for (int mt = 0; mt < 4; mt++)
                ldsm_x4(stg + kofs + (uint32_t)(a_off + mt * 16 * LDH5) * 2u,
                        ah[mt][0], ah[mt][1], ah[mt][2], ah[mt][3]);
#pragma unroll
            for (int p = 0; p < 2; p++)
                ldsm_x4(stg + kofs + (uint32_t)(ACH5 + b_off + p * 16 * LDH5) * 2u,
                        bh[p*2][0], bh[p*2][1], bh[p*2+1][0], bh[p*2+1][1]);

#pragma unroll
            for (int mt = 0; mt < 4; mt++)
#pragma unroll
                for (int nt = 0; nt < 4; nt++)
                    mma_f16(acc[mt][nt], ah[mt], bh[nt][0], bh[nt][1]);
        }

        // issue next-next stage into the buffer just consumed
        if (s + 2 < S) {
            __syncthreads();                     // all warps done reading buf
            issue_stage(s + 2, s & 1);
            cp_commit();
        }
    }

    // ---- epilogue ----
    if (Cf0) {
        float* C = blockIdx.z ? Cf1 : Cf0;
#pragma unroll
        for (int mt = 0; mt < 4; mt++) {
            int row0 = m0 + wm + mt * 16 + (lane >> 2);
#pragma unroll
            for (int nt = 0; nt < 4; nt++) {
                int col = n0 + wn + nt * 8 + (lane & 3) * 2;
                float b0 = 0.f, b1 = 0.f;
                if (bias) { b0 = __ldg(bias + col); b1 = __ldg(bias + col + 1); }
                float2 v0 = make_float2(acc[mt][nt][0] + b0, acc[mt][nt][1] + b1);
                float2 v1 = make_float2(acc[mt][nt][2] + b0, acc[mt][nt][3] + b1);
                *(float2*)(C + (size_t)row0 * N + col)       = v0;
                *(float2*)(C + (size_t)(row0 + 8) * N + col) = v1;
            }
        }
    } else {
        // fold attention scale into q/qo chunks (tile-uniform: 128 | 768)
        float sc = 1.f;
        if (qkv_scale) sc = (n0 < 768) ? -0.125f : (n0 < 1536 ? 0.125f : 1.f);
        __half* C = blockIdx.z ? Ch1 : Ch0;
#pragma unroll
        for (int mt = 0; mt < 4; mt++) {
            int row0 = m0 + wm + mt * 16 + (lane >> 2);
#pragma unroll
            for (int nt = 0; nt < 4; nt++) {
                int col = n0 + wn + nt * 8 + (lane & 3) * 2;
                *(uint32_t*)(C + (size_t)row0 * N + col) =
                    pack_h2(__float2half_rn(acc[mt][nt][0] * sc),
                            __float2half_rn(acc[mt][nt][1] * sc));
                *(uint32_t*)(C + (size_t)(row0 + 8) * N + col) =
                    pack_h2(__float2half_rn(acc[mt][nt][2] * sc),
                            __float2half_rn(acc[mt][nt][3] * sc));
            }
        }
    }
}

// ============================================================
// Dual-softmax flash attention, pure fp16 operands (fp32 accum).
// Q pre-scaled (+-hd^-0.5) by the QKV epilogue.
// Q/K/V via cp.async; V row-major [j][d], fragments via ldsm.trans.
// ATT_SMEM padded above 116736 B to force 1 CTA/SM (R9 lesson).
// (runs at ~312 TF/s effective -- unchanged)
// ============================================================
#define AQS 72
#define OQ1 0
#define OQ2 (128*AQS)
#define OKV (2*128*AQS)
#define KVB (2*64*AQS)                  // per buffer: K, V
#define ATT_SMEM 117760                 // padded: > 233472/2 -> 1 CTA/SM

__global__ __launch_bounds__(256, 1) void attention_mma()
{
    extern __shared__ __align__(16) __half sh[];
    const uint32_t sb = smem_u32(sh);
    const int tid  = threadIdx.x;
    const int wid  = tid >> 5;
    const int lane = tid & 31;
    const int wm   = wid * 16;

    const int b    = blockIdx.z;
    const int h    = blockIdx.y >> 1;
    const int pair = blockIdx.y & 1;
    const int q0   = blockIdx.x * 128;
    const int hoff = h * HD;

    const __half* bx = g_qkvx_h + (size_t)b * SEQ * QKV_DIM;
    const __half* by = g_qkvy_h + (size_t)b * SEQ * QKV_DIM;

    const __half *Q1src, *Q2src, *Ksrc;
    __half* outp;
    if (pair == 0) { Q1src = bx + C_DIM; Q2src = by;  Ksrc = bx + 2 * C_DIM; outp = g_attx_h; }
    else           { Q1src = by + C_DIM; Q2src = bx;  Ksrc = by + 2 * C_DIM; outp = g_atty_h; }
    const __half* Vsrc = bx + 3 * C_DIM;   // vy = vx in the reference
    Q1src += hoff; Q2src += hoff; Ksrc += hoff; Vsrc += hoff;

    // ---- issue Q tiles (one-time, 8 cp.async/thread) ----
    {
        const __half* qs[2] = { Q1src, Q2src };
#pragma unroll
        for (int a = 0; a < 2; a++)
#pragma unroll
            for (int j = 0; j < 4; j++) {
                int cid = tid + j * 256;         // 0..1023
                int row = cid >> 3;              // 0..127
                int c8  = (cid & 7) << 3;        // 0..56
                cp_async16(sb + (uint32_t)(a * 128 * AQS + row * AQS + c8) * 2u,
                           qs[a] + (size_t)(q0 + row) * QKV_DIM + c8);
            }
    }

    // KV tile: 64 rows x 64 halves per tensor -> 512 slots -> 2/thread/tensor
    auto issue_kv = [&](int kt, int buf) {
        const int j0 = kt * 64;
        const int nb = OKV + buf * KVB;
#pragma unroll
        for (int j = 0; j < 2; j++) {
            int cid = tid + j * 256;             // 0..511
            int row = cid >> 3;                  // 0..63
            int c8  = (cid & 7) << 3;            // 0..56
            cp_async16(sb + (uint32_t)(nb + row * AQS + c8) * 2u,
                       Ksrc + (size_t)(j0 + row) * QKV_DIM + c8);
            cp_async16(sb + (uint32_t)(nb + 64 * AQS + row * AQS + c8) * 2u,
                       Vsrc + (size_t)(j0 + row) * QKV_DIM + c8);
        }
    };

    issue_kv(0, 0);
    cp_commit();   // group 0: Q + KV tile 0

    float o1[8][4], o2[8][4];
#pragma unroll
    for (int d = 0; d < 8; d++)
#pragma unroll
        for (int r = 0; r < 4; r++) { o1[d][r] = 0.f; o2[d][r] = 0.f; }
    float m1lo = -1e30f, m1hi = -1e30f, l1lo = 0.f, l1hi = 0.f;
    float m2lo = -1e30f, m2hi = -1e30f, l2lo = 0.f, l2hi = 0.f;

    const uint32_t a_base = (uint32_t)((wm + (lane & 15)) * AQS + ((lane >> 4) << 3)) * 2u;
    const uint32_t b_base = (uint32_t)((((lane >> 4) << 3) + (lane & 7)) * AQS
                                       + (((lane >> 3) & 1) << 3)) * 2u;
    const uint32_t v_base = (uint32_t)(((((lane >> 3) & 1) << 3) + (lane & 7)) * AQS
                                       + ((lane >> 4) << 3)) * 2u;

    for (int kt = 0; kt < 16; kt++) {
        const uint32_t kvb = (uint32_t)(OKV + (kt & 1) * KVB) * 2u;

        if (kt < 15) { issue_kv(kt + 1, (kt + 1) & 1); cp_commit(); cp_wait1(); }
        else         { cp_wait0(); }
        __syncthreads();

        // ---- S = Q K^T (fp16 x fp16 -> fp32; scale pre-folded) ----
        float s1[8][4], s2[8][4];
#pragma unroll
        for (int n = 0; n < 8; n++)
#pragma unroll
            for (int r = 0; r < 4; r++) { s1[n][r] = 0.f; s2[n][r] = 0.f; }

#pragma unroll
        for (int ks = 0; ks < 4; ks++) {
            const uint32_t kofs = (uint32_t)(ks * 16) * 2u;
            uint32_t a1h[4], a2h[4];
            ldsm_x4(sb + (uint32_t)(OQ1*2) + a_base + kofs, a1h[0], a1h[1], a1h[2], a1h[3]);
            ldsm_x4(sb + (uint32_t)(OQ2*2) + a_base + kofs, a2h[0], a2h[1], a2h[2], a2h[3]);
#pragma unroll
            for (int jt = 0; jt < 4; jt++) {
                uint32_t rb = sb + kvb + b_base + (uint32_t)(jt * 16 * AQS) * 2u + kofs;
                uint32_t bh[2][2];
                ldsm_x4(rb, bh[0][0], bh[0][1], bh[1][0], bh[1][1]);
#pragma unroll
                for (int q = 0; q < 2; q++) {
                    int nt = jt * 2 + q;
                    mma_f16(s1[nt], a1h, bh[q][0], bh[q][1]);
                    mma_f16(s2[nt], a2h, bh[q][0], bh[q][1]);
                }
            }
        }

        // ---- online softmax (per stream), P as fp16 ----
        uint32_t p1h[8][2], p2h[8][2];
        {
            float mxlo = -1e30f, mxhi = -1e30f;
#pragma unroll
            for (int n = 0; n < 8; n++) {
                mxlo = fmaxf(mxlo, fmaxf(s1[n][0], s1[n][1]));
                mxhi = fmaxf(mxhi, fmaxf(s1[n][2], s1[n][3]));
            }
            mxlo = fmaxf(mxlo, __shfl_xor_sync(0xffffffffu, mxlo, 1));
            mxlo = fmaxf(mxlo, __shfl_xor_sync(0xffffffffu, mxlo, 2));
            mxhi = fmaxf(mxhi, __shfl_xor_sync(0xffffffffu, mxhi, 1));
            mxhi = fmaxf(mxhi, __shfl_xor_sync(0xffffffffu, mxhi, 2));
            float mnlo = fmaxf(m1lo, mxlo), mnhi = fmaxf(m1hi, mxhi);
            float clo = __expf(m1lo - mnlo), chi = __expf(m1hi - mnhi);
            m1lo = mnlo; m1hi = mnhi;
            float sl = 0.f, shh = 0.f;
#pragma unroll
            for (int n = 0; n < 8; n++) {
                float p0 = __expf(s1[n][0] - mnlo);
                float p1 = __expf(s1[n][1] - mnlo);
                float p2 = __expf(s1[n][2] - mnhi);
                float p3 = __expf(s1[n][3] - mnhi);
                sl += p0 + p1; shh += p2 + p3;
                p1h[n][0] = pack_h2(__float2half_rn(p0), __float2half_rn(p1));
                p1h[n][1] = pack_h2(__float2half_rn(p2), __float2half_rn(p3));
            }
            sl  += __shfl_xor_sync(0xffffffffu, sl, 1);
            sl  += __shfl_xor_sync(0xffffffffu, sl, 2);
            shh += __shfl_xor_sync(0xffffffffu, shh, 1);
            shh += __shfl_xor_sync(0xffffffffu, shh, 2);
            l1lo = l1lo * clo + sl; l1hi = l1hi * chi + shh;
#pragma unroll
            for (int d = 0; d < 8; d++) {
                o1[d][0] *= clo; o1[d][1] *= clo;
                o1[d][2] *= chi; o1[d][3] *= chi;
            }
        }
        {
            float mxlo = -1e30f, mxhi = -1e30f;
#pragma unroll
            for (int n = 0; n < 8; n++) {
                mxlo = fmaxf(mxlo, fmaxf(s2[n][0], s2[n][1]));
                mxhi = fmaxf(mxhi, fmaxf(s2[n][2], s2[n][3]));
            }
            mxlo = fmaxf(mxlo, __shfl_xor_sync(0xffffffffu, mxlo, 1));
            mxlo = fmaxf(mxlo, __shfl_xor_sync(0xffffffffu, mxlo, 2));
            mxhi = fmaxf(mxhi, __shfl_xor_sync(0xffffffffu, mxhi, 1));
            mxhi = fmaxf(mxhi, __shfl_xor_sync(0xffffffffu, mxhi, 2));
            float mnlo = fmaxf(m2lo, mxlo), mnhi = fmaxf(m2hi, mxhi);
            float clo = __expf(m2lo - mnlo), chi = __expf(m2hi - mnhi);
            m2lo = mnlo; m2hi = mnhi;
            float sl = 0.f, shh = 0.f;
#pragma unroll
            for (int n = 0; n < 8; n++) {
                float p0 = __expf(s2[n][0] - mnlo);
                float p1 = __expf(s2[n][1] - mnlo);
                float p2 = __expf(s2[n][2] - mnhi);
                float p3 = __expf(s2[n][3] - mnhi);
                sl += p0 + p1; shh += p2 + p3;
                p2h[n][0] = pack_h2(__float2half_rn(p0), __float2half_rn(p1));
                p2h[n][1] = pack_h2(__float2half_rn(p2), __float2half_rn(p3));
            }
            sl  += __shfl_xor_sync(0xffffffffu, sl, 1);
            sl  += __shfl_xor_sync(0xffffffffu, sl, 2);
            shh += __shfl_xor_sync(0xffffffffu, shh, 1);
            shh += __shfl_xor_sync(0xffffffffu, shh, 2);
            l2lo = l2lo * clo + sl; l2hi = l2hi * chi + shh;
#pragma unroll
            for (int d = 0; d < 8; d++) {
                o2[d][0] *= clo; o2[d][1] *= clo;
                o2[d][2] *= chi; o2[d][3] *= chi;
            }
        }

        // ---- O += P V (V row-major [j][d], ldsm.trans) ----
        const uint32_t vb = kvb + (uint32_t)(64 * AQS) * 2u;
#pragma unroll
        for (int ks = 0; ks < 4; ks++) {
            uint32_t a1f[4] = { p1h[2*ks][0], p1h[2*ks][1], p1h[2*ks+1][0], p1h[2*ks+1][1] };
            uint32_t a2f[4] = { p2h[2*ks][0], p2h[2*ks][1], p2h[2*ks+1][0], p2h[2*ks+1][1] };
            const uint32_t jrow = (uint32_t)(ks * 16 * AQS) * 2u;
#pragma unroll
            for (int dt2 = 0; dt2 < 4; dt2++) {
                uint32_t ra = sb + vb + v_base + jrow + (uint32_t)(dt2 * 16) * 2u;
                uint32_t vh[2][2];
                ldsm_x4_t(ra, vh[0][0], vh[0][1], vh[1][0], vh[1][1]);
#pragma unroll
                for (int q = 0; q < 2; q++) {
                    int dt = dt2 * 2 + q;
                    mma_f16(o1[dt], a1f, vh[q][0], vh[q][1]);
                    mma_f16(o2[dt], a2f, vh[q][0], vh[q][1]);
                }
            }
        }

        if (kt < 15) __syncthreads();   // protect buffer overwrite by next issue
    }

    // ---- epilogue: out = O1/l1 + O2/l2 (fp16) ----
    const float i1lo = 1.f / l1lo, i1hi = 1.f / l1hi;
    const float i2lo = 1.f / l2lo, i2hi = 1.f / l2hi;
    __half* obase = outp + (size_t)b * SEQ * C_DIM;
    const int r0 = q0 + wm + (lane >> 2);
    const int cb = hoff + (lane & 3) * 2;
#pragma unroll
    for (int dt = 0; dt < 8; dt++) {
        int col = cb + dt * 8;
        float v0 = o1[dt][0] * i1lo + o2[dt][0] * i2lo;
        float v1 = o1[dt][1] * i1lo + o2[dt][1] * i2lo;
        float v2 = o1[dt][2] * i1hi + o2[dt][2] * i2hi;
        float v3 = o1[dt][3] * i1hi + o2[dt][3] * i2hi;
        *(uint32_t*)(obase + (size_t)r0 * C_DIM + col) =
            pack_h2(__float2half_rn(v0), __float2half_rn(v1));
        *(uint32_t*)(obase + (size_t)(r0 + 8) * C_DIM + col) =
            pack_h2(__float2half_rn(v2), __float2half_rn(v3));
    }
}

// ============================================================
extern "C" void kernel_launch(void* const* d_in, const int* in_sizes, int n_in,
                              void* d_out, int out_size)
{
    const float* x      = (const float*)d_in[0];
    const float* y      = (const float*)d_in[1];
    const float* w_qkv  = (const float*)d_in[2];
    const float* w_proj = (const float*)d_in[3];
    const float* b_proj = (const float*)d_in[4];
    float* out = (float*)d_out;

    __half *xh, *yh, *wqh, *wph, *qxh, *qyh, *axh, *ayh;
    cudaGetSymbolAddress((void**)&xh,  g_x_h);
    cudaGetSymbolAddress((void**)&yh,  g_y_h);
    cudaGetSymbolAddress((void**)&wqh, g_wqkv_h);
    cudaGetSymbolAddress((void**)&wph, g_wproj_h);
    cudaGetSymbolAddress((void**)&qxh, g_qkvx_h);
    cudaGetSymbolAddress((void**)&qyh, g_qkvy_h);
    cudaGetSymbolAddress((void**)&axh, g_attx_h);
    cudaGetSymbolAddress((void**)&ayh, g_atty_h);

    cudaFuncSetAttribute(gemm_mma,
                         cudaFuncAttributeMaxDynamicSharedMemorySize, GEMM_SMEM);
    cudaFuncSetAttribute(attention_mma,
                         cudaFuncAttributeMaxDynamicSharedMemorySize, ATT_SMEM);

    // 0) fp32 -> fp16 converts (single fused launch, 4 float4/thread)
    const int nx = M_ROWS*C_DIM/4, nw = QKV_DIM*C_DIM/4, np = C_DIM*C_DIM/4;
    cvt4_kernel<<<(nx + nx + nw + np + 1023)/1024, 256>>>(
        x, xh, nx, y, yh, nx, w_qkv, wqh, nw, w_proj, wph, np);

    // 1) QKV projections, fp16 out, scale folded; y skips unused vy
    dim3 g1(QKV_DIM / 128, M_ROWS / 128, 2);
    gemm_mma<<<g1, 256, GEMM_SMEM>>>(xh, yh, wqh, nullptr,
                                     nullptr, nullptr, qxh, qyh,
                                     M_ROWS, QKV_DIM, C_DIM, 2304, 1);

    // 2) fused dual-softmax attention (pure fp16, scale pre-folded)
    attention_mma<<<dim3(SEQ / 128, HEADS * 2, BATCH), 256, ATT_SMEM>>>();

    // 3) output projections + bias, fp32 out
    dim3 g2(C_DIM / 128, M_ROWS / 128, 2);
    gemm_mma<<<g2, 256, GEMM_SMEM>>>(axh, ayh, wph, b_proj,
                                     out, out + (size_t)M_ROWS * C_DIM,
                                     nullptr, nullptr,
                                     M_ROWS, C_DIM, C_DIM, C_DIM, 0);
}